// round 12
// baseline (speedup 1.0000x reference)
#include <cuda_runtime.h>
#include <cstdint>

// FPS on GB300, round 8: TWO batches per CTA, software-pipelined so each
// batch's L2 exchange settles under the other batch's compute.
// 64 CTAs = 4 groups x 16 ranks; group handles batches 2g, 2g+1.
// Coords SMEM-resident (2 x 96KB), min-dist register-resident.
// Per step (one per batch, 3 syncthreads total):
//   updA -> warpredA -> bar1 -> warp0: ctaredA + publishA(tag s+1)
//   updB -> warpredB -> bar2 -> warp0: ctaredB + publishB; pollA->resA;
//                                      pollB->resB
//   bar3 -> lastA=resA, lastB=resB
// Exchange slots double-buffered by parity. WAR chain (formal): rank r reads
// slotA[p](s) before r's bar3(s) < r's bar2(s+1) < r's tagB(s+1) (st.release)
// <= my pollB(s+1) < my bar3(s+1) < my publishA(s+2) overwrite of slotA[p].
// Release on tagB also orders each rank's earlier tagA/payload stores, so
// passing pollB(s) implies every rank's A-data(s) is globally visible.
// Bit-exactness vs reference (rel_err 0.0 rounds 1-7): add.rn/mul.rn.f32x2,
// mul-then-add order, first-index tie-break at every reduce level.

#define NPTS   131072
#define BATCH  8
#define NSAMP  4096
#define GRP    16
#define NT     512
#define PPC    (NPTS / GRP)          // 8192
#define QPT    (PPC / (4 * NT))      // 4
#define BIGF   1e10f

// L2 exchange: [batch][parity][rank] = {xy, zv, tag|gi, pad}.
__device__ unsigned long long g_ex[BATCH][2][GRP][4];

#define ADD2(o, a, b) asm("add.rn.f32x2 %0, %1, %2;" : "=l"(o) : "l"(a), "l"(b))
#define MUL2(o, a, b) asm("mul.rn.f32x2 %0, %1, %2;" : "=l"(o) : "l"(a), "l"(b))
#define PACK2(o, lo, hi) asm("mov.b64 %0, {%1, %2};" : "=l"(o) : "f"(lo), "f"(hi))
#define UNPACK2(lo, hi, in) asm("mov.b64 {%0, %1}, %2;" : "=f"(lo), "=f"(hi) : "l"(in))

static __device__ __forceinline__ void st_rlx_gpu(unsigned long long* p,
                                                  unsigned long long v) {
    asm volatile("st.relaxed.gpu.global.u64 [%0], %1;" :: "l"(p), "l"(v) : "memory");
}
static __device__ __forceinline__ void st_rel_gpu(unsigned long long* p,
                                                  unsigned long long v) {
    asm volatile("st.release.gpu.global.u64 [%0], %1;" :: "l"(p), "l"(v) : "memory");
}
static __device__ __forceinline__ unsigned long long ld_acq_gpu(
    const unsigned long long* p) {
    unsigned long long v;
    asm volatile("ld.acquire.gpu.global.u64 %0, [%1];" : "=l"(v) : "l"(p) : "memory");
    return v;
}
static __device__ __forceinline__ unsigned long long ld_rlx_gpu(
    const unsigned long long* p) {
    unsigned long long v;
    asm volatile("ld.relaxed.gpu.global.u64 %0, [%1];" : "=l"(v) : "l"(p) : "memory");
    return v;
}
static __device__ __forceinline__ unsigned long long f2_to_u64(float a, float b) {
    unsigned long long r;
    asm("mov.b64 %0, {%1, %2};" : "=l"(r) : "f"(a), "f"(b));
    return r;
}

// Distance update + thread-local argmax for one batch (SMEM coords, reg md).
static __device__ __forceinline__ void upd_batch(
    const float* __restrict__ smx, const float* __restrict__ smy,
    const float* __restrict__ smz, float4* md,
    float lx, float ly, float lz, int tid,
    unsigned& out_vbits, int& out_idx)
{
    unsigned long long NX, NY, NZ;
    {
        float nx = -lx, ny = -ly, nz = -lz;  // x + (-l) == x - l bit-exact (rn)
        PACK2(NX, nx, nx); PACK2(NY, ny, ny); PACK2(NZ, nz, nz);
    }
#pragma unroll
    for (int j = 0; j < QPT; j++) {
        const int q4 = j * NT + tid;
        float4 X = ((const float4*)smx)[q4];
        float4 Y = ((const float4*)smy)[q4];
        float4 Z = ((const float4*)smz)[q4];
        unsigned long long xa, xb, ya, yb, za, zb, sa, sb;
        PACK2(xa, X.x, X.y); PACK2(xb, X.z, X.w);
        PACK2(ya, Y.x, Y.y); PACK2(yb, Y.z, Y.w);
        PACK2(za, Z.x, Z.y); PACK2(zb, Z.z, Z.w);
        ADD2(xa, xa, NX); MUL2(xa, xa, xa);
        ADD2(ya, ya, NY); MUL2(ya, ya, ya);
        ADD2(za, za, NZ); MUL2(za, za, za);
        ADD2(sa, xa, ya);          // (dx^2 + dy^2)
        ADD2(sa, sa, za);          // + dz^2 — same order as jnp.sum
        ADD2(xb, xb, NX); MUL2(xb, xb, xb);
        ADD2(yb, yb, NY); MUL2(yb, yb, yb);
        ADD2(zb, zb, NZ); MUL2(zb, zb, zb);
        ADD2(sb, xb, yb);
        ADD2(sb, sb, zb);
        float d0, d1, d2, d3;
        UNPACK2(d0, d1, sa);
        UNPACK2(d2, d3, sb);
        md[j].x = fminf(md[j].x, d0);
        md[j].y = fminf(md[j].y, d1);
        md[j].z = fminf(md[j].z, d2);
        md[j].w = fminf(md[j].w, d3);
    }
    // FMNMX tree + descending equality scan => lowest index wins ties.
    float bestv = md[0].x;
#pragma unroll
    for (int j = 0; j < QPT; j++) {
        bestv = fmaxf(fmaxf(bestv, fmaxf(md[j].x, md[j].y)),
                      fmaxf(md[j].z, md[j].w));
    }
    int besti = 0;
#pragma unroll
    for (int j = QPT - 1; j >= 0; j--) {
        const int ib = 4 * (j * NT + tid);
        if (md[j].w == bestv) besti = ib + 3;
        if (md[j].z == bestv) besti = ib + 2;
        if (md[j].y == bestv) besti = ib + 1;
        if (md[j].x == bestv) besti = ib + 0;
    }
    // Warp reduce: REDUX max on bits (nonneg fp32 monotonic), min idx.
    unsigned vb   = __float_as_uint(bestv);
    unsigned wmax = __reduce_max_sync(0xffffffffu, vb);
    out_vbits = wmax;
    out_idx   = (int)__reduce_min_sync(0xffffffffu,
                    vb == wmax ? (unsigned)besti : 0xffffffffu);
}

// warp0: CTA reduce over 32 warp candidates, publish to L2 slot.
static __device__ __forceinline__ void ctared_publish(
    const unsigned* wv, const unsigned* wi,
    const float* smx, const float* smy, const float* smz,
    unsigned long long* slot, int base, int s, int lane)
{
    unsigned v2   = wv[lane];
    unsigned i2   = wi[lane];
    unsigned cmax = __reduce_max_sync(0xffffffffu, v2);
    unsigned csel = __reduce_min_sync(0xffffffffu,
                                      v2 == cmax ? i2 : 0xffffffffu);
    if (lane == 0) {
        float cx = smx[csel], cy = smy[csel], cz = smz[csel];
        unsigned gi = (unsigned)(base + (int)csel);
        st_rlx_gpu(&slot[0], f2_to_u64(cx, cy));
        st_rlx_gpu(&slot[1], f2_to_u64(cz, __uint_as_float(cmax)));
        st_rel_gpu(&slot[2],
                   ((unsigned long long)(unsigned)(s + 1) << 32) | gi);
    }
}

// warp0: poll 16 peer tags, reduce, write winner xyz to res[].
static __device__ __forceinline__ void poll_reduce(
    const unsigned long long* slots_base,   // &g_ex[batch][p][0][0]
    int s, int lane, float* res)
{
    const unsigned long long want = (unsigned long long)(unsigned)(s + 1);
    const unsigned long long* peer = slots_base + (lane < GRP ? lane : 0) * 4;
    unsigned long long t = 0;
    bool ok;
    do {
        if (lane < GRP) t = ld_acq_gpu(&peer[2]);
        ok = (lane >= GRP) || ((t >> 32) == want);
    } while (!__all_sync(0xffffffffu, ok));

    unsigned gv = 0u, ggi = 0xffffffffu;
    float gx = 0.f, gy = 0.f, gz = 0.f;
    if (lane < GRP) {
        unsigned long long xy = ld_rlx_gpu(&peer[0]);
        unsigned long long zv = ld_rlx_gpu(&peer[1]);
        float fv;
        UNPACK2(gx, gy, xy);
        UNPACK2(gz, fv, zv);
        gv  = __float_as_uint(fv);
        ggi = (unsigned)t;
    }
    unsigned gmax = __reduce_max_sync(0xffffffffu, gv);
    unsigned gsel = __reduce_min_sync(
        0xffffffffu, (lane < GRP && gv == gmax) ? ggi : 0xffffffffu);
    unsigned ball = __ballot_sync(0xffffffffu,
                                  lane < GRP && gv == gmax && ggi == gsel);
    const int src = __ffs(ball) - 1;
    gx = __shfl_sync(0xffffffffu, gx, src);
    gy = __shfl_sync(0xffffffffu, gy, src);
    gz = __shfl_sync(0xffffffffu, gz, src);
    if (lane == 0) { res[0] = gx; res[1] = gy; res[2] = gz; }
}

__global__ void __launch_bounds__(NT, 1)
fps_dual(const float* __restrict__ pts, float* __restrict__ out)
{
    extern __shared__ float sm[];
    float*    smxA = sm;                    // [PPC] each
    float*    smyA = sm + PPC;
    float*    smzA = sm + 2 * PPC;
    float*    smxB = sm + 3 * PPC;
    float*    smyB = sm + 4 * PPC;
    float*    smzB = sm + 5 * PPC;
    unsigned* wvA  = (unsigned*)(sm + 6 * PPC);   // [32]
    unsigned* wiA  = wvA + 32;
    unsigned* wvB  = wiA + 32;
    unsigned* wiB  = wvB + 32;
    float*    resA = (float*)(wiB + 32);          // [4]
    float*    resB = resA + 4;

    const int tid  = threadIdx.x;
    const int lane = tid & 31;
    const int warp = tid >> 5;
    const int grp  = blockIdx.x >> 4;       // group 0..3
    const int rank = blockIdx.x & 15;
    const int bA   = 2 * grp;
    const int bB   = 2 * grp + 1;
    const float* PA = pts + (size_t)bA * NPTS * 3;
    const float* PB = pts + (size_t)bB * NPTS * 3;
    const int base = rank * PPC;

    // Zero my tags (both parities, both batches).
    if (tid == 0) {
        st_rlx_gpu(&g_ex[bA][0][rank][2], 0ull);
        st_rlx_gpu(&g_ex[bA][1][rank][2], 0ull);
        st_rlx_gpu(&g_ex[bB][0][rank][2], 0ull);
        st_rlx_gpu(&g_ex[bB][1][rank][2], 0ull);
    }

    // Load both batches' coords into SMEM (SoA).
    for (int i = tid; i < PPC; i += NT) {
        const float* ga = PA + (size_t)(base + i) * 3;
        smxA[i] = ga[0]; smyA[i] = ga[1]; smzA[i] = ga[2];
        const float* gb = PB + (size_t)(base + i) * 3;
        smxB[i] = gb[0]; smyB[i] = gb[1]; smzB[i] = gb[2];
    }
    if (tid < 32) {
        wvA[tid] = 0u; wiA[tid] = 0xffffffffu;   // pad lanes 16..31
        wvB[tid] = 0u; wiB[tid] = 0xffffffffu;
    }

    float4 mdA[QPT], mdB[QPT];
#pragma unroll
    for (int j = 0; j < QPT; j++) {
        mdA[j] = make_float4(BIGF, BIGF, BIGF, BIGF);
        mdB[j] = make_float4(BIGF, BIGF, BIGF, BIGF);
    }

    __syncthreads();

    float lxA = PA[0], lyA = PA[1], lzA = PA[2];   // last_idx init = 0
    float lxB = PB[0], lyB = PB[1], lzB = PB[2];

    for (int s = 0; s < NSAMP; s++) {
        const int p = s & 1;

        // Emit BEFORE update (reference scan semantics).
        if (rank == 0 && tid == 0) {
            float* oA = out + ((size_t)bA * NSAMP + s) * 3;
            oA[0] = lxA; oA[1] = lyA; oA[2] = lzA;
            float* oB = out + ((size_t)bB * NSAMP + s) * 3;
            oB[0] = lxB; oB[1] = lyB; oB[2] = lzB;
        }

        // ---- A: update + warp reduce ----
        unsigned wmA; int imA;
        upd_batch(smxA, smyA, smzA, mdA, lxA, lyA, lzA, tid, wmA, imA);
        if (lane == 0) { wvA[warp] = wmA; wiA[warp] = (unsigned)imA; }
        __syncthreads();                                   // bar1

        // ---- warp0: publish A (exchange settles under B's update) ----
        if (warp == 0)
            ctared_publish(wvA, wiA, smxA, smyA, smzA,
                           &g_ex[bA][p][rank][0], base, s, lane);

        // ---- B: update + warp reduce ----
        unsigned wmB; int imB;
        upd_batch(smxB, smyB, smzB, mdB, lxB, lyB, lzB, tid, wmB, imB);
        if (lane == 0) { wvB[warp] = wmB; wiB[warp] = (unsigned)imB; }
        __syncthreads();                                   // bar2

        // ---- warp0: publish B; collect A then B ----
        if (warp == 0) {
            ctared_publish(wvB, wiB, smxB, smyB, smzB,
                           &g_ex[bB][p][rank][0], base, s, lane);
            poll_reduce(&g_ex[bA][p][0][0], s, lane, resA);
            poll_reduce(&g_ex[bB][p][0][0], s, lane, resB);
        }
        __syncthreads();                                   // bar3
        lxA = resA[0]; lyA = resA[1]; lzA = resA[2];
        lxB = resB[0]; lyB = resB[1]; lzB = resB[2];
    }
}

extern "C" void kernel_launch(void* const* d_in, const int* in_sizes, int n_in,
                              void* d_out, int out_size)
{
    (void)in_sizes; (void)n_in; (void)out_size;
    const float* pts = (const float*)d_in[0];   // point_coord (8, 131072, 3)
    float* out = (float*)d_out;                 // (8, 4096, 3)

    const size_t smem = (size_t)(6 * PPC + 4 * 32 + 8) * sizeof(float);
    cudaFuncSetAttribute(fps_dual, cudaFuncAttributeMaxDynamicSharedMemorySize,
                         (int)smem);
    fps_dual<<<(BATCH / 2) * GRP, NT, smem>>>(pts, out);
}